// round 2
// baseline (speedup 1.0000x reference)
#include <cuda_runtime.h>

// Problem constants
#define B_SZ 4096
#define T_SZ 200
#define D_SZ 64
#define P_SZ 2
#define TM1 (T_SZ - 1)   // 199

// Accumulators: [0]=step_ahead weighted sum, [1]=drift sum, [2]=global_diff sum
__device__ double g_acc[3];

__global__ void init_kernel() {
    g_acc[0] = 0.0; g_acc[1] = 0.0; g_acc[2] = 0.0;
}

// Block-level reduction of one float into a double accumulator.
__device__ __forceinline__ void block_reduce_add(float v, double* target) {
    // warp reduce
    #pragma unroll
    for (int off = 16; off > 0; off >>= 1)
        v += __shfl_down_sync(0xFFFFFFFFu, v, off);
    __shared__ float warp_sums[32];
    int lane = threadIdx.x & 31;
    int wid  = threadIdx.x >> 5;
    if (lane == 0) warp_sums[wid] = v;
    __syncthreads();
    int nwarps = (blockDim.x + 31) >> 5;
    if (wid == 0) {
        float s = (lane < nwarps) ? warp_sums[lane] : 0.0f;
        #pragma unroll
        for (int off = 16; off > 0; off >>= 1)
            s += __shfl_down_sync(0xFFFFFFFFu, s, off);
        if (lane == 0) atomicAdd(target, (double)s);
    }
}

// Step-ahead term: sum over active rows (b,t) of w_b * sum_d (cov[b,t+1,1+d] - pred[b,t,d])^2
// w_b = 1/((len-1)*D) if len>1 else 0.  Dead rows are skipped BEFORE any loads.
// 16 lanes per row; lane loads float4 of pred (aligned) + 4 scalars of cov.
__global__ void step_kernel(const float* __restrict__ pred,
                            const float* __restrict__ cov,
                            const int*   __restrict__ lengths) {
    const int groups_per_block = blockDim.x >> 4;           // 16 lanes/group
    const int gid    = blockIdx.x * groups_per_block + (threadIdx.x >> 4);
    const int lane   = threadIdx.x & 15;
    const int n_grps = gridDim.x * groups_per_block;
    const int n_rows = B_SZ * TM1;

    float local = 0.0f;
    for (int row = gid; row < n_rows; row += n_grps) {
        int b = row / TM1;
        int t = row - b * TM1;
        int len = lengths[b];
        if (t >= len - 1) continue;                         // skip: no loads issued
        float w = 1.0f / ((float)(len - 1) * (float)D_SZ);

        const float4 p = *reinterpret_cast<const float4*>(
            pred + (size_t)row * D_SZ + (lane << 2));
        const float* c = cov + (size_t)b * T_SZ * (D_SZ + 1)
                             + (size_t)(t + 1) * (D_SZ + 1) + 1 + (lane << 2);
        float d0 = c[0] - p.x;
        float d1 = c[1] - p.y;
        float d2 = c[2] - p.z;
        float d3 = c[3] - p.w;
        local += w * (d0 * d0 + d1 * d1 + d2 * d2 + d3 * d3);
    }
    block_reduce_add(local, &g_acc[0]);
}

// Drift + global-diff terms over pred_params [B, T, P=2].
// One thread per (b,t): float2 load; drift uses next timestep's float2.
__global__ void pred_kernel(const float* __restrict__ pred,
                            const float* __restrict__ theta) {
    const float th0 = theta[0];
    const float th1 = theta[1];
    const float inv_th0 = 1.0f / th0;
    const float inv_th1 = 1.0f / th1;

    const int n = B_SZ * T_SZ;
    const int stride = gridDim.x * blockDim.x;

    float drift = 0.0f;
    float gdiff = 0.0f;
    for (int i = blockIdx.x * blockDim.x + threadIdx.x; i < n; i += stride) {
        int t = i % T_SZ;
        float2 x = reinterpret_cast<const float2*>(pred)[i];
        float e0 = x.x * inv_th0 - 1.0f;
        float e1 = x.y * inv_th1 - 1.0f;
        gdiff += e0 * e0 + e1 * e1;
        if (t < T_SZ - 1) {
            float2 y = reinterpret_cast<const float2*>(pred)[i + 1];
            float d0 = x.x - y.x;
            float d1 = x.y - y.y;
            drift += d0 * d0 + d1 * d1;
        }
    }
    block_reduce_add(drift, &g_acc[1]);
    block_reduce_add(gdiff, &g_acc[2]);
}

__global__ void finalize_kernel(float* __restrict__ out) {
    double step  = g_acc[0] / (double)B_SZ;
    double drift = g_acc[1] / ((double)B_SZ * (double)TM1 * (double)P_SZ);
    double gdiff = g_acc[2] / ((double)B_SZ * (double)T_SZ * (double)P_SZ);
    out[0] = (float)(1.0 * step + 0.1 * drift + 0.01 * gdiff);
}

extern "C" void kernel_launch(void* const* d_in, const int* in_sizes, int n_in,
                              void* d_out, int out_size) {
    const float* global_theta = (const float*)d_in[0];
    const float* pred_params  = (const float*)d_in[1];
    // d_in[2] = hidden_states: UNUSED by the reference
    const float* step_preds   = (const float*)d_in[3];
    const float* cov_trajs    = (const float*)d_in[4];
    const int*   lengths      = (const int*)d_in[5];
    float* out = (float*)d_out;

    init_kernel<<<1, 1>>>();
    step_kernel<<<2048, 256>>>(step_preds, cov_trajs, lengths);
    pred_kernel<<<1024, 256>>>(pred_params, global_theta);
    finalize_kernel<<<1, 1>>>(out);
}